// round 7
// baseline (speedup 1.0000x reference)
#include <cuda_runtime.h>
#include <cuda_bf16.h>
#include <cstdint>

// Problem constants
#define NN      262144
#define HID     512
#define GATES   64
#define NG      1024

// Scratch (static __device__ globals — no allocation)
__device__ float g_gate[(size_t)NN * GATES];            // 64 MB gate logits
__device__ float g_w[NN];                               // per-node pooled weight
__device__ __nv_bfloat16 g_bh[GATES * HID];             // W^T hi, [n][k] row-major
__device__ __nv_bfloat16 g_bl[GATES * HID];             // W^T lo

// ---------------------------------------------------------------------------
// Helpers
// ---------------------------------------------------------------------------
__device__ __forceinline__ uint32_t smem_u32(const void* p) {
    uint32_t a;
    asm("{ .reg .u64 t; cvta.to.shared.u64 t, %1; cvt.u32.u64 %0, t; }" : "=r"(a) : "l"(p));
    return a;
}
// SW128 swizzle — self-consistent between staging stores and ldmatrix reads.
#define SW128(o) ((o) ^ ((((uint32_t)(o)) >> 3) & 0x70u))

__device__ __forceinline__ void ldm_x4(uint32_t r[4], uint32_t addr) {
    asm volatile("ldmatrix.sync.aligned.m8n8.x4.shared.b16 {%0,%1,%2,%3}, [%4];"
                 : "=r"(r[0]), "=r"(r[1]), "=r"(r[2]), "=r"(r[3]) : "r"(addr));
}
__device__ __forceinline__ void mma_bf16(float d[4], const uint32_t a[4],
                                         const uint32_t b[2]) {
    asm volatile(
        "mma.sync.aligned.m16n8k16.row.col.f32.bf16.bf16.f32 "
        "{%0,%1,%2,%3}, {%4,%5,%6,%7}, {%8,%9}, {%0,%1,%2,%3};"
        : "+f"(d[0]), "+f"(d[1]), "+f"(d[2]), "+f"(d[3])
        : "r"(a[0]), "r"(a[1]), "r"(a[2]), "r"(a[3]), "r"(b[0]), "r"(b[1]));
}

// SMEM layout: A tiles 128 rows x 128B (64 bf16), B tiles 64 rows x 128B
#define SM_AHI    0
#define SM_ALO    16384
#define SM_BHI    32768
#define SM_BLO    40960
#define SM_TOTAL  49152

// ---------------------------------------------------------------------------
// Kernel 0: split/transpose W [512k][64n] fp32 -> g_bh/g_bl [64n][512k] bf16
// One element per thread; grid sized to fill the chip (prev: occ 11.9%).
// ---------------------------------------------------------------------------
__global__ void prep_w(const float* __restrict__ W) {
    int idx = blockIdx.x * 128 + threadIdx.x;
    if (idx < HID * GATES) {
        int k = idx >> 6, n = idx & 63;
        float v = W[idx];
        __nv_bfloat16 hi = __float2bfloat16(v);
        __nv_bfloat16 lo = __float2bfloat16(v - __bfloat162float(hi));
        g_bh[n * HID + k] = hi;
        g_bl[n * HID + k] = lo;
    }
}

// ---------------------------------------------------------------------------
// Kernel 1: gate = x @ W via mma.sync bf16 hi/lo split (3-pass, fp32-accurate)
// (byte-identical to the 318us passing version)
// ---------------------------------------------------------------------------
__global__ __launch_bounds__(256) void gemm_tc(const float* __restrict__ x) {
    extern __shared__ __align__(1024) char smem[];
    const uint32_t sb = smem_u32(smem);
    const int tid = threadIdx.x, wid = tid >> 5, lane = tid & 31;
    const int rowBase = blockIdx.x * 128;
    const int wm = (wid >> 1) * 32, wn = (wid & 1) * 32;
    const int sub = lane >> 3, rr = lane & 7;

    float acc[2][4][4];
#pragma unroll
    for (int mt = 0; mt < 2; mt++)
#pragma unroll
        for (int nt = 0; nt < 4; nt++)
#pragma unroll
            for (int q = 0; q < 4; q++) acc[mt][nt][q] = 0.f;

    for (int c = 0; c < 8; c++) {
#pragma unroll
        for (int it = 0; it < 8; it++) {
            int idx = tid + it * 256;
            int row = idx >> 4, q = idx & 15;
            float4 v = *(const float4*)(x + (size_t)(rowBase + row) * HID + c * 64 + q * 4);
            __nv_bfloat16 h0 = __float2bfloat16(v.x), h1 = __float2bfloat16(v.y);
            __nv_bfloat16 h2 = __float2bfloat16(v.z), h3 = __float2bfloat16(v.w);
            __nv_bfloat16 l0 = __float2bfloat16(v.x - __bfloat162float(h0));
            __nv_bfloat16 l1 = __float2bfloat16(v.y - __bfloat162float(h1));
            __nv_bfloat16 l2 = __float2bfloat16(v.z - __bfloat162float(h2));
            __nv_bfloat16 l3 = __float2bfloat16(v.w - __bfloat162float(h3));
            uint32_t hA = ((uint32_t)__bfloat16_as_ushort(h1) << 16) | __bfloat16_as_ushort(h0);
            uint32_t hB = ((uint32_t)__bfloat16_as_ushort(h3) << 16) | __bfloat16_as_ushort(h2);
            uint32_t lA = ((uint32_t)__bfloat16_as_ushort(l1) << 16) | __bfloat16_as_ushort(l0);
            uint32_t lB = ((uint32_t)__bfloat16_as_ushort(l3) << 16) | __bfloat16_as_ushort(l2);
            uint32_t off = SW128((uint32_t)(row * 128 + q * 8));
            *(uint2*)(smem + SM_AHI + off) = make_uint2(hA, hB);
            *(uint2*)(smem + SM_ALO + off) = make_uint2(lA, lB);
        }
#pragma unroll
        for (int it = 0; it < 2; it++) {
            int idx = tid + it * 256;
            int n = idx >> 3, j = idx & 7;
            size_t src = ((size_t)n * HID + c * 64) * 2 + j * 16;
            uint4 vh = *(const uint4*)((const char*)g_bh + src);
            uint4 vl = *(const uint4*)((const char*)g_bl + src);
            uint32_t off = SW128((uint32_t)(n * 128 + j * 16));
            *(uint4*)(smem + SM_BHI + off) = vh;
            *(uint4*)(smem + SM_BLO + off) = vl;
        }
        __syncthreads();

#pragma unroll
        for (int ks = 0; ks < 4; ks++) {
            const int kOff = ks * 16;
            uint32_t ah[2][4], al[2][4], bh[2][4], bl[2][4];
#pragma unroll
            for (int mt = 0; mt < 2; mt++) {
                uint32_t off = SW128((uint32_t)(
                    (wm + mt * 16 + (sub & 1) * 8 + rr) * 128 +
                    (kOff + (sub >> 1) * 8) * 2));
                ldm_x4(ah[mt], sb + SM_AHI + off);
                ldm_x4(al[mt], sb + SM_ALO + off);
            }
#pragma unroll
            for (int np = 0; np < 2; np++) {
                uint32_t off = SW128((uint32_t)(
                    (wn + np * 16 + (sub >> 1) * 8 + rr) * 128 +
                    (kOff + (sub & 1) * 8) * 2));
                ldm_x4(bh[np], sb + SM_BHI + off);
                ldm_x4(bl[np], sb + SM_BLO + off);
            }
#pragma unroll
            for (int mt = 0; mt < 2; mt++)
#pragma unroll
                for (int nt = 0; nt < 4; nt++) {
                    const uint32_t* pbh = &bh[nt >> 1][(nt & 1) * 2];
                    const uint32_t* pbl = &bl[nt >> 1][(nt & 1) * 2];
                    mma_bf16(acc[mt][nt], ah[mt], pbh);
                    mma_bf16(acc[mt][nt], ah[mt], pbl);
                    mma_bf16(acc[mt][nt], al[mt], pbh);
                }
        }
        __syncthreads();
    }

#pragma unroll
    for (int mt = 0; mt < 2; mt++)
#pragma unroll
        for (int nt = 0; nt < 4; nt++) {
            int r = rowBase + wm + mt * 16 + (lane >> 2);
            int cc = wn + nt * 8 + (lane & 3) * 2;
            *(float2*)&g_gate[(size_t)r * 64 + cc] =
                make_float2(acc[mt][nt][0], acc[mt][nt][1]);
            *(float2*)&g_gate[(size_t)(r + 8) * 64 + cc] =
                make_float2(acc[mt][nt][2], acc[mt][nt][3]);
        }
}

// ---------------------------------------------------------------------------
// batch index: int64 (x64) or int32 autodetect + binary search
// ---------------------------------------------------------------------------
__device__ __forceinline__ long long load_batch(const void* b, bool is64, int i) {
    return is64 ? ((const long long*)b)[i] : (long long)((const int*)b)[i];
}
__device__ __forceinline__ bool batch_is64(const void* b) {
    long long probe = ((const long long*)b)[NN / 2 - 1];
    return (probe >= 0 && probe < (long long)NG);
}
__device__ int lower_bound_batch(const void* b, bool is64, long long val) {
    int lo = 0, hi = NN;
    while (lo < hi) {
        int mid = (lo + hi) >> 1;
        if (load_batch(b, is64, mid) < val) lo = mid + 1; else hi = mid;
    }
    return lo;
}

// ---------------------------------------------------------------------------
// Kernel 2a: per-graph stats (online max+sum, ONE gate read) + node weights
// grid = 1024, 256 threads. Writes g_w.
// ---------------------------------------------------------------------------
__global__ __launch_bounds__(256) void stats_weights(const void* __restrict__ batch) {
    __shared__ float redM[256];
    __shared__ float redS[256];
    __shared__ float sm_m[64];
    __shared__ float sm_r[64];
    __shared__ int seg[2];

    const int tid = threadIdx.x;
    const int g = blockIdx.x;

    if (tid == 0) {
        bool is64 = batch_is64(batch);
        seg[0] = lower_bound_batch(batch, is64, (long long)g);
        seg[1] = lower_bound_batch(batch, is64, (long long)g + 1);
    }
    __syncthreads();
    const int st = seg[0], en = seg[1];

    // ---- online segment max + exp-sum per gate column (single gate pass) ----
    const int k = tid & 63, grp = tid >> 6;   // 64 cols x 4 row-groups
    float m = -3.402823466e38f, s = 0.f;
    for (int i = st + grp; i < en; i += 4) {
        float v = g_gate[(size_t)i * 64 + k];
        float nm = fmaxf(m, v);
        s = s * __expf(m - nm) + __expf(v - nm);
        m = nm;
    }
    redM[tid] = m;
    redS[tid] = s;
    __syncthreads();
    if (tid < 64) {
        float m0 = redM[tid], m1 = redM[tid + 64], m2 = redM[tid + 128], m3 = redM[tid + 192];
        float mm = fmaxf(fmaxf(m0, m1), fmaxf(m2, m3));
        float ss = 0.f;   // guard s>0 so empty groups (m=-inf) never make NaN
        float s0 = redS[tid], s1 = redS[tid + 64], s2 = redS[tid + 128], s3 = redS[tid + 192];
        if (s0 > 0.f) ss += s0 * __expf(m0 - mm);
        if (s1 > 0.f) ss += s1 * __expf(m1 - mm);
        if (s2 > 0.f) ss += s2 * __expf(m2 - mm);
        if (s3 > 0.f) ss += s3 * __expf(m3 - mm);
        sm_m[tid] = mm;
        sm_r[tid] = 1.0f / (ss + 1e-16f) * (1.0f / 64.0f);   // fold mean into recip
    }
    __syncthreads();

    // ---- node weights: w_i = mean_k softmax(gate)[i,k]  (second gate pass) ----
    const int warp = tid >> 5, lane = tid & 31;
    const float mA = sm_m[lane], mB = sm_m[lane + 32];
    const float rA = sm_r[lane], rB = sm_r[lane + 32];
    for (int i = st + warp; i < en; i += 8) {
        float w = __expf(g_gate[(size_t)i * 64 + lane] - mA) * rA
                + __expf(g_gate[(size_t)i * 64 + 32 + lane] - mB) * rB;
#pragma unroll
        for (int off = 16; off; off >>= 1) w += __shfl_xor_sync(0xffffffffu, w, off);
        if (lane == 0) g_w[i] = w;
    }
}

// ---------------------------------------------------------------------------
// Kernel 2b: weighted pooling. grid = 2048 = (graph, hidden-half).
// Each thread owns one hidden column; rows unrolled x8 for MLP.
// ---------------------------------------------------------------------------
__global__ __launch_bounds__(256) void pool(const float* __restrict__ x,
                                            const void* __restrict__ batch,
                                            float* __restrict__ out) {
    __shared__ int seg[2];
    const int tid = threadIdx.x;
    const int g = blockIdx.x >> 1;
    const int col = ((blockIdx.x & 1) << 8) + tid;

    if (tid == 0) {
        bool is64 = batch_is64(batch);
        seg[0] = lower_bound_batch(batch, is64, (long long)g);
        seg[1] = lower_bound_batch(batch, is64, (long long)g + 1);
    }
    __syncthreads();
    const int st = seg[0], en = seg[1];

    float a = 0.f;
    const float* p = x + (size_t)st * HID + col;
    int i = st;
    for (; i + 8 <= en; i += 8) {
        float w0 = g_w[i],     w1 = g_w[i + 1], w2 = g_w[i + 2], w3 = g_w[i + 3];
        float w4 = g_w[i + 4], w5 = g_w[i + 5], w6 = g_w[i + 6], w7 = g_w[i + 7];
        a += w0 * p[0]        + w1 * p[HID]     + w2 * p[2 * HID] + w3 * p[3 * HID]
           + w4 * p[4 * HID]  + w5 * p[5 * HID] + w6 * p[6 * HID] + w7 * p[7 * HID];
        p += 8 * HID;
    }
    for (; i < en; i++) { a += g_w[i] * p[0]; p += HID; }
    out[(size_t)g * HID + col] = a;   // covers all of d_out (incl. empty graphs)
}

// ---------------------------------------------------------------------------
extern "C" void kernel_launch(void* const* d_in, const int* in_sizes, int n_in,
                              void* d_out, int out_size) {
    const float* x = nullptr;
    const float* W = nullptr;
    const void* batch = nullptr;
    for (int i = 0; i < n_in; i++) {
        if (in_sizes[i] == NN * HID)          x = (const float*)d_in[i];
        else if (in_sizes[i] == HID * GATES)  W = (const float*)d_in[i];
        else if (in_sizes[i] == NN)           batch = d_in[i];
    }
    float* out = (float*)d_out;

    cudaFuncSetAttribute(gemm_tc, cudaFuncAttributeMaxDynamicSharedMemorySize, SM_TOTAL);

    prep_w<<<(HID * GATES + 127) / 128, 128>>>(W);
    gemm_tc<<<NN / 128, 256, SM_TOTAL>>>(x);
    stats_weights<<<NG, 256>>>(batch);
    pool<<<NG * 2, 256>>>(x, batch, out);
}

// round 10
// speedup vs baseline: 1.1591x; 1.1591x over previous
#include <cuda_runtime.h>
#include <cuda_bf16.h>
#include <cstdint>

// Problem constants
#define NN      262144
#define HID     512
#define GATES   64
#define NG      1024

// Scratch (static __device__ globals — no allocation)
__device__ float g_gate[(size_t)NN * GATES];            // 64 MB gate logits
__device__ float g_w[NN];                               // per-node pooled weight
__device__ __nv_bfloat16 g_bh[GATES * HID];             // W^T hi, [n][k] row-major
__device__ __nv_bfloat16 g_bl[GATES * HID];             // W^T lo

// ---------------------------------------------------------------------------
// Helpers
// ---------------------------------------------------------------------------
__device__ __forceinline__ uint32_t smem_u32(const void* p) {
    uint32_t a;
    asm("{ .reg .u64 t; cvta.to.shared.u64 t, %1; cvt.u32.u64 %0, t; }" : "=r"(a) : "l"(p));
    return a;
}
// SW128 swizzle — self-consistent between staging stores and ldmatrix reads.
#define SW128(o) ((o) ^ ((((uint32_t)(o)) >> 3) & 0x70u))

__device__ __forceinline__ void ldm_x4(uint32_t r[4], uint32_t addr) {
    asm volatile("ldmatrix.sync.aligned.m8n8.x4.shared.b16 {%0,%1,%2,%3}, [%4];"
                 : "=r"(r[0]), "=r"(r[1]), "=r"(r[2]), "=r"(r[3]) : "r"(addr));
}
__device__ __forceinline__ void mma_bf16(float d[4], const uint32_t a[4],
                                         const uint32_t b[2]) {
    asm volatile(
        "mma.sync.aligned.m16n8k16.row.col.f32.bf16.bf16.f32 "
        "{%0,%1,%2,%3}, {%4,%5,%6,%7}, {%8,%9}, {%0,%1,%2,%3};"
        : "+f"(d[0]), "+f"(d[1]), "+f"(d[2]), "+f"(d[3])
        : "r"(a[0]), "r"(a[1]), "r"(a[2]), "r"(a[3]), "r"(b[0]), "r"(b[1]));
}
// packed f32x2 -> bf16x2 (h0 = bf(a), h1 = bf(b))
__device__ __forceinline__ uint32_t cvt_bf16x2(float a, float b) {
    uint32_t r;
    asm("cvt.rn.satfinite.bf16x2.f32 %0, %1, %2;" : "=r"(r) : "f"(b), "f"(a));
    return r;
}

// SMEM layout: A tiles 128 rows x 128B (64 bf16), B tiles 64 rows x 128B
#define SM_AHI    0
#define SM_ALO    16384
#define SM_BHI    32768
#define SM_BLO    40960
#define SM_TOTAL  49152

// ---------------------------------------------------------------------------
// Kernel 0: split/transpose W [512k][64n] fp32 -> g_bh/g_bl [64n][512k] bf16
// ---------------------------------------------------------------------------
__global__ void prep_w(const float* __restrict__ W) {
    int idx = blockIdx.x * 128 + threadIdx.x;
    if (idx < HID * GATES) {
        int k = idx >> 6, n = idx & 63;
        float v = W[idx];
        __nv_bfloat16 hi = __float2bfloat16(v);
        __nv_bfloat16 lo = __float2bfloat16(v - __bfloat162float(hi));
        g_bh[n * HID + k] = hi;
        g_bl[n * HID + k] = lo;
    }
}

// ---------------------------------------------------------------------------
// Kernel 1: gate = x @ W via mma.sync bf16 hi/lo split (3-pass, fp32-accurate)
// This round: software-pipelined (register prefetch of next K-chunk overlaps
// MMA compute) + packed bf16x2 conversion (half the cvt ops).
// ---------------------------------------------------------------------------
__global__ __launch_bounds__(256) void gemm_tc(const float* __restrict__ x) {
    extern __shared__ __align__(1024) char smem[];
    const uint32_t sb = smem_u32(smem);
    const int tid = threadIdx.x, wid = tid >> 5, lane = tid & 31;
    const int rowBase = blockIdx.x * 128;
    const int wm = (wid >> 1) * 32, wn = (wid & 1) * 32;
    const int sub = lane >> 3, rr = lane & 7;

    // this thread's staging coordinates (fixed across chunks)
    const int sIdx0 = tid;                 // it*256 + tid
    float4 px[8];

    float acc[2][4][4];
#pragma unroll
    for (int mt = 0; mt < 2; mt++)
#pragma unroll
        for (int nt = 0; nt < 4; nt++)
#pragma unroll
            for (int q = 0; q < 4; q++) acc[mt][nt][q] = 0.f;

    // prefetch chunk 0
#pragma unroll
    for (int it = 0; it < 8; it++) {
        int idx = sIdx0 + it * 256, row = idx >> 4, q = idx & 15;
        px[it] = *(const float4*)(x + (size_t)(rowBase + row) * HID + q * 4);
    }

    for (int c = 0; c < 8; c++) {
        // ---- convert + store A chunk (from prefetched registers) ----
#pragma unroll
        for (int it = 0; it < 8; it++) {
            int idx = sIdx0 + it * 256, row = idx >> 4, q = idx & 15;
            float4 v = px[it];
            uint32_t hA = cvt_bf16x2(v.x, v.y);
            uint32_t hB = cvt_bf16x2(v.z, v.w);
            float l0 = v.x - __uint_as_float(hA << 16);
            float l1 = v.y - __uint_as_float(hA & 0xFFFF0000u);
            float l2 = v.z - __uint_as_float(hB << 16);
            float l3 = v.w - __uint_as_float(hB & 0xFFFF0000u);
            uint32_t lA = cvt_bf16x2(l0, l1);
            uint32_t lB = cvt_bf16x2(l2, l3);
            uint32_t off = SW128((uint32_t)(row * 128 + q * 8));
            *(uint2*)(smem + SM_AHI + off) = make_uint2(hA, hB);
            *(uint2*)(smem + SM_ALO + off) = make_uint2(lA, lB);
        }
        // ---- stage B chunk (small; L2-resident after first blocks) ----
#pragma unroll
        for (int it = 0; it < 2; it++) {
            int idx = sIdx0 + it * 256, n = idx >> 3, j = idx & 7;
            size_t src = ((size_t)n * HID + c * 64) * 2 + j * 16;
            uint4 vh = *(const uint4*)((const char*)g_bh + src);
            uint4 vl = *(const uint4*)((const char*)g_bl + src);
            uint32_t off = SW128((uint32_t)(n * 128 + j * 16));
            *(uint4*)(smem + SM_BHI + off) = vh;
            *(uint4*)(smem + SM_BLO + off) = vl;
        }
        __syncthreads();

        // ---- prefetch next chunk's A (overlaps the MMA block below) ----
        if (c + 1 < 8) {
#pragma unroll
            for (int it = 0; it < 8; it++) {
                int idx = sIdx0 + it * 256, row = idx >> 4, q = idx & 15;
                px[it] = *(const float4*)(x + (size_t)(rowBase + row) * HID +
                                          (c + 1) * 64 + q * 4);
            }
        }

        // ---- compute: 4 k-steps of 16; 3 passes (AhBh + AhBl + AlBh) ----
#pragma unroll
        for (int ks = 0; ks < 4; ks++) {
            const int kOff = ks * 16;
            uint32_t ah[2][4], al[2][4], bh[2][4], bl[2][4];
#pragma unroll
            for (int mt = 0; mt < 2; mt++) {
                uint32_t off = SW128((uint32_t)(
                    (wm + mt * 16 + (sub & 1) * 8 + rr) * 128 +
                    (kOff + (sub >> 1) * 8) * 2));
                ldm_x4(ah[mt], sb + SM_AHI + off);
                ldm_x4(al[mt], sb + SM_ALO + off);
            }
#pragma unroll
            for (int np = 0; np < 2; np++) {
                uint32_t off = SW128((uint32_t)(
                    (wn + np * 16 + (sub >> 1) * 8 + rr) * 128 +
                    (kOff + (sub & 1) * 8) * 2));
                ldm_x4(bh[np], sb + SM_BHI + off);
                ldm_x4(bl[np], sb + SM_BLO + off);
            }
#pragma unroll
            for (int mt = 0; mt < 2; mt++)
#pragma unroll
                for (int nt = 0; nt < 4; nt++) {
                    const uint32_t* pbh = &bh[nt >> 1][(nt & 1) * 2];
                    const uint32_t* pbl = &bl[nt >> 1][(nt & 1) * 2];
                    mma_bf16(acc[mt][nt], ah[mt], pbh);
                    mma_bf16(acc[mt][nt], ah[mt], pbl);
                    mma_bf16(acc[mt][nt], al[mt], pbh);
                }
        }
        __syncthreads();
    }

#pragma unroll
    for (int mt = 0; mt < 2; mt++)
#pragma unroll
        for (int nt = 0; nt < 4; nt++) {
            int r = rowBase + wm + mt * 16 + (lane >> 2);
            int cc = wn + nt * 8 + (lane & 3) * 2;
            *(float2*)&g_gate[(size_t)r * 64 + cc] =
                make_float2(acc[mt][nt][0], acc[mt][nt][1]);
            *(float2*)&g_gate[(size_t)(r + 8) * 64 + cc] =
                make_float2(acc[mt][nt][2], acc[mt][nt][3]);
        }
}

// ---------------------------------------------------------------------------
// batch index: int64 (x64) or int32 autodetect + binary search
// ---------------------------------------------------------------------------
__device__ __forceinline__ long long load_batch(const void* b, bool is64, int i) {
    return is64 ? ((const long long*)b)[i] : (long long)((const int*)b)[i];
}
__device__ __forceinline__ bool batch_is64(const void* b) {
    long long probe = ((const long long*)b)[NN / 2 - 1];
    return (probe >= 0 && probe < (long long)NG);
}
__device__ int lower_bound_batch(const void* b, bool is64, long long val) {
    int lo = 0, hi = NN;
    while (lo < hi) {
        int mid = (lo + hi) >> 1;
        if (load_batch(b, is64, mid) < val) lo = mid + 1; else hi = mid;
    }
    return lo;
}

// ---------------------------------------------------------------------------
// Kernel 2: FUSED per-graph online softmax stats + node weights + pooling.
// grid = 1024, 256 threads. Two gate passes + one x pass; no kernel boundary
// between stats and pooling (per-graph phases pipeline across blocks).
// ---------------------------------------------------------------------------
__global__ __launch_bounds__(256) void softmax_pool(const float* __restrict__ x,
                                                    const void* __restrict__ batch,
                                                    float* __restrict__ out) {
    __shared__ float redM[256];
    __shared__ float redS[256];
    __shared__ float sm_m[64];
    __shared__ float sm_r[64];
    __shared__ int seg[2];

    const int tid = threadIdx.x;
    const int g = blockIdx.x;

    if (tid == 0) {
        bool is64 = batch_is64(batch);
        seg[0] = lower_bound_batch(batch, is64, (long long)g);
        seg[1] = lower_bound_batch(batch, is64, (long long)g + 1);
    }
    __syncthreads();
    const int st = seg[0], en = seg[1];

    // ---- Pass A: online segment max + exp-sum per gate column ----
    const int k = tid & 63, grp = tid >> 6;   // 64 cols x 4 row-groups
    float m = -3.402823466e38f, s = 0.f;
    for (int i = st + grp; i < en; i += 4) {
        float v = g_gate[(size_t)i * 64 + k];
        float nm = fmaxf(m, v);
        s = s * __expf(m - nm) + __expf(v - nm);
        m = nm;
    }
    redM[tid] = m;
    redS[tid] = s;
    __syncthreads();
    if (tid < 64) {
        float m0 = redM[tid], m1 = redM[tid + 64], m2 = redM[tid + 128], m3 = redM[tid + 192];
        float mm = fmaxf(fmaxf(m0, m1), fmaxf(m2, m3));
        float ss = 0.f;   // guard s>0 so empty groups (m=-inf) never make NaN
        float s0 = redS[tid], s1 = redS[tid + 64], s2 = redS[tid + 128], s3 = redS[tid + 192];
        if (s0 > 0.f) ss += s0 * __expf(m0 - mm);
        if (s1 > 0.f) ss += s1 * __expf(m1 - mm);
        if (s2 > 0.f) ss += s2 * __expf(m2 - mm);
        if (s3 > 0.f) ss += s3 * __expf(m3 - mm);
        sm_m[tid] = mm;
        sm_r[tid] = 1.0f / (ss + 1e-16f) * (1.0f / 64.0f);   // fold mean into recip
    }
    __syncthreads();

    // ---- Pass B: node weights w_i = mean_k softmax(gate)[i,k] ----
    const int warp = tid >> 5, lane = tid & 31;
    const float mA = sm_m[lane], mB = sm_m[lane + 32];
    const float rA = sm_r[lane], rB = sm_r[lane + 32];
    for (int i = st + warp; i < en; i += 8) {
        float w = __expf(g_gate[(size_t)i * 64 + lane] - mA) * rA
                + __expf(g_gate[(size_t)i * 64 + 32 + lane] - mB) * rB;
#pragma unroll
        for (int off = 16; off; off >>= 1) w += __shfl_xor_sync(0xffffffffu, w, off);
        if (lane == 0) g_w[i] = w;
    }
    __syncthreads();   // g_w visible block-wide

    // ---- Pass C: out[g] = sum_i w_i * x_i (2 cols/thread, 8-row unroll) ----
    float a0 = 0.f, a1 = 0.f;
    const float* p = x + (size_t)st * HID + tid;
    int i = st;
    for (; i + 8 <= en; i += 8) {
        float w0 = g_w[i],     w1 = g_w[i + 1], w2 = g_w[i + 2], w3 = g_w[i + 3];
        float w4 = g_w[i + 4], w5 = g_w[i + 5], w6 = g_w[i + 6], w7 = g_w[i + 7];
        a0 += w0 * p[0]           + w1 * p[HID]           + w2 * p[2 * HID]       + w3 * p[3 * HID]
            + w4 * p[4 * HID]     + w5 * p[5 * HID]       + w6 * p[6 * HID]       + w7 * p[7 * HID];
        a1 += w0 * p[256]         + w1 * p[HID + 256]     + w2 * p[2 * HID + 256] + w3 * p[3 * HID + 256]
            + w4 * p[4 * HID + 256] + w5 * p[5 * HID + 256] + w6 * p[6 * HID + 256] + w7 * p[7 * HID + 256];
        p += 8 * HID;
    }
    for (; i < en; i++) {
        float w = g_w[i];
        a0 += w * p[0];
        a1 += w * p[256];
        p += HID;
    }
    out[(size_t)g * HID + tid]       = a0;   // covers all of d_out (incl. empty graphs)
    out[(size_t)g * HID + tid + 256] = a1;
}

// ---------------------------------------------------------------------------
extern "C" void kernel_launch(void* const* d_in, const int* in_sizes, int n_in,
                              void* d_out, int out_size) {
    const float* x = nullptr;
    const float* W = nullptr;
    const void* batch = nullptr;
    for (int i = 0; i < n_in; i++) {
        if (in_sizes[i] == NN * HID)          x = (const float*)d_in[i];
        else if (in_sizes[i] == HID * GATES)  W = (const float*)d_in[i];
        else if (in_sizes[i] == NN)           batch = d_in[i];
    }
    float* out = (float*)d_out;

    cudaFuncSetAttribute(gemm_tc, cudaFuncAttributeMaxDynamicSharedMemorySize, SM_TOTAL);

    prep_w<<<(HID * GATES + 127) / 128, 128>>>(W);
    gemm_tc<<<NN / 128, 256, SM_TOTAL>>>(x);
    softmax_pool<<<NG, 256>>>(x, batch, out);
}